// round 15
// baseline (speedup 1.0000x reference)
#include <cuda_runtime.h>
#include <cuda_fp16.h>
#include <cstdint>

// Problem constants
#define BB   4
#define LL   2048
#define AD   1024
#define NH   16
#define HD   64
#define MM   (BB*LL)   // 8192

// ---------------------------------------------------------------------------
// Scratch (device globals)
// ---------------------------------------------------------------------------
__device__ __half g_acts [3 * MM * AD];    // fp16 activations q|k|v
__device__ __half g_wt   [4 * AD * AD];    // weights^T fp16 (q,k,v,o)
__device__ __half g_heads[3 * MM * AD];    // head planes Q(prescaled)|K|V
__device__ __half g_ao   [MM * AD];        // attention output fp16 [M,1024]

// ---------------------------------------------------------------------------
// Helpers (plain sm_103-legal: cp.async, ldmatrix, mma.sync)
// ---------------------------------------------------------------------------
__device__ __forceinline__ uint32_t smem_u32(const void* p) {
    uint32_t a;
    asm("{ .reg .u64 t; cvta.to.shared.u64 t, %1; cvt.u32.u64 %0, t; }" : "=r"(a) : "l"(p));
    return a;
}
#define CP_COMMIT()  asm volatile("cp.async.commit_group;" ::: "memory")
#define CP_WAIT(n)   asm volatile("cp.async.wait_group %0;" :: "n"(n) : "memory")

__device__ __forceinline__ uint32_t pack_h2(__half a, __half b) {
    return (uint32_t)__half_as_ushort(a) | ((uint32_t)__half_as_ushort(b) << 16);
}
__device__ __forceinline__ uint32_t h2_u(__half2 v) { return *reinterpret_cast<uint32_t*>(&v); }
__device__ __forceinline__ __half2  u_h2(uint32_t v) { return *reinterpret_cast<__half2*>(&v); }

__device__ __forceinline__ void ldm_x4(uint32_t& r0, uint32_t& r1, uint32_t& r2, uint32_t& r3,
                                       uint32_t addr) {
    asm volatile("ldmatrix.sync.aligned.m8n8.x4.shared.b16 {%0,%1,%2,%3}, [%4];"
                 : "=r"(r0), "=r"(r1), "=r"(r2), "=r"(r3) : "r"(addr));
}
__device__ __forceinline__ void ldm_x4_t(uint32_t& r0, uint32_t& r1, uint32_t& r2, uint32_t& r3,
                                         uint32_t addr) {
    asm volatile("ldmatrix.sync.aligned.m8n8.x4.trans.shared.b16 {%0,%1,%2,%3}, [%4];"
                 : "=r"(r0), "=r"(r1), "=r"(r2), "=r"(r3) : "r"(addr));
}
// fp32-accumulator mma
__device__ __forceinline__ void mma16816(float* d, const uint32_t* a, uint32_t b0, uint32_t b1) {
    asm volatile(
        "mma.sync.aligned.m16n8k16.row.col.f32.f16.f16.f32 "
        "{%0,%1,%2,%3}, {%4,%5,%6,%7}, {%8,%9}, {%0,%1,%2,%3};"
        : "+f"(d[0]), "+f"(d[1]), "+f"(d[2]), "+f"(d[3])
        : "r"(a[0]), "r"(a[1]), "r"(a[2]), "r"(a[3]), "r"(b0), "r"(b1));
}
// fp16-accumulator mma (d packed half2 x2; layout == A-fragment layout)
__device__ __forceinline__ void mma16816h(uint32_t* d, const uint32_t* a, uint32_t b0, uint32_t b1) {
    asm volatile(
        "mma.sync.aligned.m16n8k16.row.col.f16.f16.f16.f16 "
        "{%0,%1}, {%2,%3,%4,%5}, {%6,%7}, {%0,%1};"
        : "+r"(d[0]), "+r"(d[1])
        : "r"(a[0]), "r"(a[1]), "r"(a[2]), "r"(a[3]), "r"(b0), "r"(b1));
}

// ---------------------------------------------------------------------------
// conv_act fused: 3 inputs fp32 [M,1024] -> fp16, selected by blockIdx.y
// ---------------------------------------------------------------------------
__global__ void conv_act3(const float* __restrict__ X0, const float* __restrict__ X1,
                          const float* __restrict__ X2, __half* __restrict__ Y)
{
    const int z = blockIdx.y;
    const float* X = (z == 0) ? X0 : (z == 1) ? X1 : X2;
    int m = blockIdx.x;
    int c = threadIdx.x * 4;
    float4 v = *reinterpret_cast<const float4*>(X + (size_t)m * AD + c);
    uint2 o;
    o.x = pack_h2(__float2half_rn(v.x), __float2half_rn(v.y));
    o.y = pack_h2(__float2half_rn(v.z), __float2half_rn(v.w));
    *reinterpret_cast<uint2*>(Y + (size_t)z * MM * AD + (size_t)m * AD + c) = o;
}

// ---------------------------------------------------------------------------
// conv_wt fused: 4 weights W[K][N] fp32 -> Wt[N][K] fp16, selected by blockIdx.z
// ---------------------------------------------------------------------------
__global__ void conv_wt4(const float* __restrict__ W0, const float* __restrict__ W1,
                         const float* __restrict__ W2, const float* __restrict__ W3,
                         __half* __restrict__ WtBase)
{
    __shared__ float s[32][33];
    const int z = blockIdx.z;
    const float* W = (z == 0) ? W0 : (z == 1) ? W1 : (z == 2) ? W2 : W3;
    __half* Wt = WtBase + (size_t)z * AD * AD;
    int n0 = blockIdx.x * 32;
    int k0 = blockIdx.y * 32;
    int tx = threadIdx.x, ty = threadIdx.y;   // (32, 8)
#pragma unroll
    for (int i = 0; i < 4; ++i)
        s[ty + 8 * i][tx] = W[(size_t)(k0 + ty + 8 * i) * AD + n0 + tx];
    __syncthreads();
#pragma unroll
    for (int i = 0; i < 4; ++i) {
        int n = n0 + ty + 8 * i;
        int k = k0 + tx;
        Wt[(size_t)n * AD + k] = __float2half_rn(s[tx][ty + 8 * i]);
    }
}

// ---------------------------------------------------------------------------
// fp16 mma GEMM core — 3-stage cp.async pipeline, single sync per K-chunk.
// CTA 128x128, K chunks 64. Stage s: A at s*32768, B at s*32768+16384.
// smem 96KB, 2 CTAs/SM (192KB <= 228KB).
// ---------------------------------------------------------------------------
#define GK_NC 16
#define G_STAGE 32768
#define G_SMEM  (3 * G_STAGE)   // 98304

__device__ __forceinline__ void load_tile_cp(uint32_t sbase, uint32_t soff,
                                             const __half* __restrict__ g,
                                             int row0, int kc, int tid)
{
#pragma unroll
    for (int i = 0; i < 4; ++i) {
        int idx = i * 256 + tid;
        int r = idx >> 3, seg = idx & 7;
        const char* src = (const char*)g + ((size_t)(row0 + r) * AD + kc) * 2 + seg * 16;
        uint32_t dst = sbase + soff + r * 128 + ((seg * 16) ^ ((r & 7) * 16));
        asm volatile("cp.async.cg.shared.global [%0], [%1], 16;" :: "r"(dst), "l"(src));
    }
}

__device__ __forceinline__ void gemm_body(const __half* __restrict__ A,
                                          const __half* __restrict__ Bt,
                                          const float* __restrict__ bias,
                                          float* __restrict__ C,
                                          __half* __restrict__ outH,
                                          float oscale,
                                          char* smem)
{
    const uint32_t sbase = smem_u32(smem);
    const int tid  = threadIdx.x;
    const int warp = tid >> 5;
    const int lane = tid & 31;
    const int bn = blockIdx.x * 128;
    const int bm = blockIdx.y * 128;

    const int wm0 = (warp >> 2) * 64;
    const int wn0 = (warp & 3) * 32;

    float d[4][4][4];
#pragma unroll
    for (int im = 0; im < 4; ++im)
#pragma unroll
        for (int jt = 0; jt < 4; ++jt)
#pragma unroll
            for (int q = 0; q < 4; ++q) d[im][jt][q] = 0.f;

    uint32_t a_rb[4], a_sw[4];
#pragma unroll
    for (int im = 0; im < 4; ++im) {
        int row = wm0 + im * 16 + (lane & 15);
        a_rb[im] = row * 128;
        a_sw[im] = (row & 7) * 16;
    }
    const uint32_t a_kb = (lane >> 4) * 16;
    uint32_t b_rb[2], b_sw[2];
#pragma unroll
    for (int jn = 0; jn < 2; ++jn) {
        int row = wn0 + jn * 16 + (lane & 7) + ((lane >> 4) << 3);
        b_rb[jn] = row * 128;
        b_sw[jn] = (row & 7) * 16;
    }
    const uint32_t b_kb = ((lane >> 3) & 1) * 16;

    // prologue: stages 0 and 1 in flight
    load_tile_cp(sbase, 0,         A,  bm, 0, tid);
    load_tile_cp(sbase, 16384,     Bt, bn, 0, tid);
    CP_COMMIT();
    load_tile_cp(sbase, G_STAGE,         A,  bm, 64, tid);
    load_tile_cp(sbase, G_STAGE + 16384, Bt, bn, 64, tid);
    CP_COMMIT();

    for (int i = 0; i < GK_NC; ++i) {
        if (i < GK_NC - 1) { CP_WAIT(1); } else { CP_WAIT(0); }
        __syncthreads();   // chunk i visible to all; buffer (i+2)%3 retired

        if (i + 2 < GK_NC) {
            const uint32_t ns = ((i + 2) % 3) * G_STAGE;
            load_tile_cp(sbase, ns,         A,  bm, (i + 2) * 64, tid);
            load_tile_cp(sbase, ns + 16384, Bt, bn, (i + 2) * 64, tid);
            CP_COMMIT();
        }

        const uint32_t aoff = (i % 3) * G_STAGE;
        const uint32_t boff = aoff + 16384;

#pragma unroll
        for (int ks = 0; ks < 4; ++ks) {
            const uint32_t kb = ks * 32;
            uint32_t af[4][4];
#pragma unroll
            for (int im = 0; im < 4; ++im)
                ldm_x4(af[im][0], af[im][1], af[im][2], af[im][3],
                       sbase + aoff + a_rb[im] + ((kb + a_kb) ^ a_sw[im]));
            uint32_t bf[4][2];
#pragma unroll
            for (int jn = 0; jn < 2; ++jn) {
                uint32_t r0, r1, r2, r3;
                ldm_x4(r0, r1, r2, r3,
                       sbase + boff + b_rb[jn] + ((kb + b_kb) ^ b_sw[jn]));
                bf[jn * 2][0] = r0; bf[jn * 2][1] = r1;
                bf[jn * 2 + 1][0] = r2; bf[jn * 2 + 1][1] = r3;
            }
#pragma unroll
            for (int im = 0; im < 4; ++im)
#pragma unroll
                for (int jt = 0; jt < 4; ++jt)
                    mma16816(d[im][jt], af[im], bf[jt][0], bf[jt][1]);
        }
    }

    if (outH == nullptr) {
#pragma unroll
        for (int jt = 0; jt < 4; ++jt) {
            const int c0 = bn + wn0 + jt * 8 + 2 * (lane & 3);
            float2 bb = *reinterpret_cast<const float2*>(bias + c0);
#pragma unroll
            for (int im = 0; im < 4; ++im) {
                const int r0 = bm + wm0 + im * 16 + (lane >> 2);
                float2 o0 = make_float2(d[im][jt][0] + bb.x, d[im][jt][1] + bb.y);
                float2 o1 = make_float2(d[im][jt][2] + bb.x, d[im][jt][3] + bb.y);
                *reinterpret_cast<float2*>(C + (size_t)r0 * AD + c0)       = o0;
                *reinterpret_cast<float2*>(C + (size_t)(r0 + 8) * AD + c0) = o1;
            }
        }
    } else {
        // fp16 head-plane epilogue: [(b*NH+h)][L][64]
#pragma unroll
        for (int jt = 0; jt < 4; ++jt) {
            const int c0 = bn + wn0 + jt * 8 + 2 * (lane & 3);
            float2 bb = *reinterpret_cast<const float2*>(bias + c0);
            const int hh = c0 >> 6, dd = c0 & 63;
#pragma unroll
            for (int im = 0; im < 4; ++im) {
                const int r0 = bm + wm0 + im * 16 + (lane >> 2);
#pragma unroll
                for (int half = 0; half < 2; ++half) {
                    const int r = r0 + half * 8;
                    float v0 = (d[im][jt][half * 2 + 0] + bb.x) * oscale;
                    float v1 = (d[im][jt][half * 2 + 1] + bb.y) * oscale;
                    size_t addr = ((size_t)((r >> 11) * NH + hh) * LL + (r & 2047)) * HD + dd;
                    *reinterpret_cast<uint32_t*>(outH + addr) =
                        pack_h2(__float2half_rn(v0), __float2half_rn(v1));
                }
            }
        }
    }
}

// Fused QKV wrapper: blockIdx.z in {0,1,2} selects the projection.
struct QkvArgs {
    const __half* A;
    const __half* W;
    const float*  bias[3];
    __half*       outH;
};

// Q prescale folds softmax scale AND log2(e) so attention works in base-2.
#define Q_PRESCALE (0.125f * 1.4426950408889634f)

__global__ __launch_bounds__(256, 2)
void gemm_qkv(QkvArgs a)
{
    extern __shared__ char smem[];
    const int z = blockIdx.z;
    const float oscale = (z == 0) ? Q_PRESCALE : 1.0f;
    gemm_body(a.A + (size_t)z * MM * AD,
              a.W + (size_t)z * AD * AD,
              a.bias[z],
              nullptr,
              a.outH + (size_t)z * MM * AD,
              oscale, smem);
}

__global__ __launch_bounds__(256, 2)
void gemm_out(const __half* __restrict__ A, const __half* __restrict__ Bt,
              const float* __restrict__ bias, float* __restrict__ C)
{
    extern __shared__ char smem[];
    gemm_body(A, Bt, bias, C, nullptr, 1.0f, smem);
}

// ---------------------------------------------------------------------------
// fp16 mma flash attention — split-KV layout at 3 CTAs/SM (R14, unchanged).
// ---------------------------------------------------------------------------
#define AT_Q   0
#define AT_BUF 8192
#define AT_SMEM (8192 + 2*32768)        // 73728 ; x3 CTAs = 216KB <= 228KB

__device__ __forceinline__ void at_load_plane(uint32_t sb, uint32_t soff,
                                              const __half* __restrict__ g,
                                              size_t pbase, int row0, int nrows, int tid)
{
    const int iters = nrows / 16;
#pragma unroll
    for (int i = 0; i < 8; ++i) {
        if (i >= iters) break;
        int idx = i * 128 + tid;
        int r = idx >> 3, seg = idx & 7;
        const char* src = (const char*)(g + pbase + (size_t)(row0 + r) * HD) + seg * 16;
        uint32_t dst = sb + soff + r * 128 + ((seg * 16) ^ ((r & 7) * 16));
        asm volatile("cp.async.cg.shared.global [%0], [%1], 16;" :: "r"(dst), "l"(src));
    }
}

__global__ __launch_bounds__(128, 3)
void attn_mma(const __half* __restrict__ Qh,
              const __half* __restrict__ Kh,
              const __half* __restrict__ Vh,
              __half* __restrict__ Oatt)
{
    extern __shared__ char smem[];
    const uint32_t sb = smem_u32(smem);
    const int tid  = threadIdx.x;
    const int warp = tid >> 5;
    const int lane = tid & 31;
    const int gidr = lane >> 2;
    const int tg   = lane & 3;
    const int qh   = warp & 1;
    const int kvh  = warp >> 1;

    const int qt = blockIdx.x, h = blockIdx.y, b = blockIdx.z;
    const size_t pbase = (size_t)(b * NH + h) * LL * HD;
    const int q0 = qt * 64;

    at_load_plane(sb, AT_Q, Qh, pbase, q0, 64, tid);
    CP_COMMIT();
    at_load_plane(sb, AT_BUF,         Kh, pbase, 0, 128, tid);
    at_load_plane(sb, AT_BUF + 16384, Vh, pbase, 0, 128, tid);
    CP_COMMIT();
    at_load_plane(sb, AT_BUF + 32768, Kh, pbase, 128, 128, tid);
    at_load_plane(sb, AT_BUF + 49152, Vh, pbase, 128, 128, tid);
    CP_COMMIT();

    const uint32_t a_kb = (lane >> 4) * 16;
    uint32_t q_off[2], q_sw[2];
#pragma unroll
    for (int im = 0; im < 2; ++im) {
        const uint32_t row = 32 * qh + 16 * im + (lane & 15);
        q_off[im] = row * 128;
        q_sw[im]  = (row & 7) * 16;
    }

    const uint32_t b_rowb = (lane & 7) + ((lane >> 4) << 3);
    const uint32_t b_kb   = ((lane >> 3) & 1) * 16;
    const uint32_t v_rowb = (lane & 15);
    const uint32_t v_cb   = (lane >> 4) * 16;

    const uint32_t ones = ((lane >> 2) == 0) ? 0x3C003C00u : 0u;

    float m[2][2];
    m[0][0] = m[0][1] = m[1][0] = m[1][1] = -1e30f;
    float O[2][8][4];
    float Ol[2][4];
#pragma unroll
    for (int im = 0; im < 2; ++im) {
#pragma unroll
        for (int jn = 0; jn < 8; ++jn)
#pragma unroll
            for (int q = 0; q < 4; ++q) O[im][jn][q] = 0.f;
#pragma unroll
        for (int q = 0; q < 4; ++q) Ol[im][q] = 0.f;
    }

    for (int ci = 0; ci < 16; ++ci) {
        if (ci < 15) { CP_WAIT(1); } else { CP_WAIT(0); }
        __syncthreads();

        const uint32_t kh_ = sb + AT_BUF + (ci & 1) * 32768;
        const uint32_t vh_ = kh_ + 16384;

        uint32_t sh[2][8][2];
#pragma unroll
        for (int im = 0; im < 2; ++im)
#pragma unroll
            for (int jn = 0; jn < 8; ++jn) { sh[im][jn][0] = 0u; sh[im][jn][1] = 0u; }

#pragma unroll
        for (int ks = 0; ks < 4; ++ks) {
            const uint32_t kb = ks * 32;
            uint32_t qf0[4], qf1[4];
            ldm_x4(qf0[0], qf0[1], qf0[2], qf0[3],
                   sb + AT_Q + q_off[0] + ((kb + a_kb) ^ q_sw[0]));
            ldm_x4(qf1[0], qf1[1], qf1[2], qf1[3],
                   sb + AT_Q + q_off[1] + ((kb + a_kb) ^ q_sw[1]));
#pragma unroll
            for (int jt = 0; jt < 4; ++jt) {
                const uint32_t row = 64 * kvh + 16 * jt + b_rowb;
                uint32_t r0, r1, r2, r3;
                ldm_x4(r0, r1, r2, r3, kh_ + row * 128 + ((kb + b_kb) ^ ((row & 7) * 16)));
                mma16816h(sh[0][2 * jt],     qf0, r0, r1);
                mma16816h(sh[0][2 * jt + 1], qf0, r2, r3);
                mma16816h(sh[1][2 * jt],     qf1, r0, r1);
                mma16816h(sh[1][2 * jt + 1], qf1, r2, r3);
            }
        }

#pragma unroll
        for (int im = 0; im < 2; ++im) {
            __half2 cx0 = u_h2(sh[im][0][0]), cx1 = u_h2(sh[im][0][1]);
#pragma unroll
            for (int jn = 1; jn < 8; ++jn) {
                cx0 = __hmax2(cx0, u_h2(sh[im][jn][0]));
                cx1 = __hmax2(cx1, u_h2(sh[im][jn][1]));
            }
            float cm0 = fmaxf(__low2float(cx0), __high2float(cx0));
            float cm1 = fmaxf(__low2float(cx1), __high2float(cx1));
            cm0 = fmaxf(cm0, __shfl_xor_sync(0xffffffffu, cm0, 1));
            cm0 = fmaxf(cm0, __shfl_xor_sync(0xffffffffu, cm0, 2));
            cm1 = fmaxf(cm1, __shfl_xor_sync(0xffffffffu, cm1, 1));
            cm1 = fmaxf(cm1, __shfl_xor_sync(0xffffffffu, cm1, 2));
            const float mn0 = fmaxf(m[im][0], cm0);
            const float mn1 = fmaxf(m[im][1], cm1);
            const float corr0 = exp2f(m[im][0] - mn0);
            const float corr1 = exp2f(m[im][1] - mn1);
            m[im][0] = mn0; m[im][1] = mn1;
#pragma unroll
            for (int jn = 0; jn < 8; ++jn) {
                O[im][jn][0] *= corr0; O[im][jn][1] *= corr0;
                O[im][jn][2] *= corr1; O[im][jn][3] *= corr1;
            }
            Ol[im][0] *= corr0; Ol[im][1] *= corr0;
            Ol[im][2] *= corr1; Ol[im][3] *= corr1;

            const __half2 mh0 = __floats2half2_rn(mn0, mn0);
            const __half2 mh1 = __floats2half2_rn(mn1, mn1);
#pragma unroll
            for (int jn = 0; jn < 8; ++jn) {
                sh[im][jn][0] = h2_u(h2exp2(__hsub2(u_h2(sh[im][jn][0]), mh0)));
                sh[im][jn][1] = h2_u(h2exp2(__hsub2(u_h2(sh[im][jn][1]), mh1)));
            }
        }

#pragma unroll
        for (int kk = 0; kk < 4; ++kk) {
            uint32_t ah0[4] = { sh[0][2*kk][0], sh[0][2*kk][1], sh[0][2*kk+1][0], sh[0][2*kk+1][1] };
            uint32_t ah1[4] = { sh[1][2*kk][0], sh[1][2*kk][1], sh[1][2*kk+1][0], sh[1][2*kk+1][1] };

            mma16816(Ol[0], ah0, ones, ones);
            mma16816(Ol[1], ah1, ones, ones);

            const uint32_t vrow = 64 * kvh + 16 * kk + v_rowb;
            const uint32_t vsw  = (vrow & 7) * 16;
            const uint32_t vaddr = vh_ + vrow * 128;
#pragma unroll
            for (int nb = 0; nb < 4; ++nb) {
                uint32_t r0, r1, r2, r3;
                ldm_x4_t(r0, r1, r2, r3, vaddr + (((uint32_t)(nb * 32) + v_cb) ^ vsw));
                mma16816(O[0][2 * nb],     ah0, r0, r1);
                mma16816(O[0][2 * nb + 1], ah0, r2, r3);
                mma16816(O[1][2 * nb],     ah1, r0, r1);
                mma16816(O[1][2 * nb + 1], ah1, r2, r3);
            }
        }

        __syncthreads();
        if (ci + 2 < 16) {
            uint32_t bb = AT_BUF + (ci & 1) * 32768;
            int row0 = (ci + 2) * 128;
            at_load_plane(sb, bb,         Kh, pbase, row0, 128, tid);
            at_load_plane(sb, bb + 16384, Vh, pbase, row0, 128, tid);
            CP_COMMIT();
        }
    }

    float lw[2][2];
#pragma unroll
    for (int im = 0; im < 2; ++im) {
        lw[im][0] = __shfl_sync(0xffffffffu, Ol[im][0], lane & 28);
        lw[im][1] = __shfl_sync(0xffffffffu, Ol[im][2], lane & 28);
    }

    if (kvh == 1) {
        float* dst = reinterpret_cast<float*>(smem + AT_BUF + qh * 9216) + lane * 72;
#pragma unroll
        for (int im = 0; im < 2; ++im)
#pragma unroll
            for (int jn = 0; jn < 8; ++jn)
#pragma unroll
                for (int q = 0; q < 4; ++q)
                    dst[im * 32 + jn * 4 + q] = O[im][jn][q];
        dst[64] = m[0][0]; dst[65] = m[0][1]; dst[66] = m[1][0]; dst[67] = m[1][1];
        dst[68] = lw[0][0]; dst[69] = lw[0][1]; dst[70] = lw[1][0]; dst[71] = lw[1][1];
    }
    __syncthreads();
    if (kvh == 0) {
        const float* src = reinterpret_cast<const float*>(smem + AT_BUF + qh * 9216) + lane * 72;
        const int colb = h * HD + 2 * tg;
#pragma unroll
        for (int im = 0; im < 2; ++im) {
#pragma unroll
            for (int half = 0; half < 2; ++half) {
                const float mA = m[im][half];
                const float mB = src[64 + im * 2 + half];
                const float ms = fmaxf(mA, mB);
                const float cA = exp2f(mA - ms);
                const float cB = exp2f(mB - ms);
                const float linv = 1.f / (lw[im][half] * cA + src[68 + im * 2 + half] * cB);
                const int r = q0 + 32 * qh + 16 * im + gidr + 8 * half;
                const int qb = half * 2;
#pragma unroll
                for (int jn = 0; jn < 8; ++jn) {
                    float v0 = (O[im][jn][qb]     * cA + src[im * 32 + jn * 4 + qb]     * cB) * linv;
                    float v1 = (O[im][jn][qb + 1] * cA + src[im * 32 + jn * 4 + qb + 1] * cB) * linv;
                    size_t addr = (size_t)(b * LL + r) * AD + colb + 8 * jn;
                    *reinterpret_cast<uint32_t*>(Oatt + addr) =
                        pack_h2(__float2half_rn(v0), __float2half_rn(v1));
                }
            }
        }
    }
}

// ---------------------------------------------------------------------------
// Launch: 5 kernels total
// ---------------------------------------------------------------------------
extern "C" void kernel_launch(void* const* d_in, const int* in_sizes, int n_in,
                              void* d_out, int out_size)
{
    const float* query = (const float*)d_in[0];
    const float* key   = (const float*)d_in[1];
    const float* value = (const float*)d_in[2];
    const float* Wq = (const float*)d_in[3];
    const float* bq = (const float*)d_in[4];
    const float* Wk = (const float*)d_in[5];
    const float* bk = (const float*)d_in[6];
    const float* Wv = (const float*)d_in[7];
    const float* bv = (const float*)d_in[8];
    const float* Wo = (const float*)d_in[9];
    const float* bo = (const float*)d_in[10];
    float* out = (float*)d_out;

    __half *pacts, *pwt, *pheads, *pao;
    cudaGetSymbolAddress((void**)&pacts,  g_acts);
    cudaGetSymbolAddress((void**)&pwt,    g_wt);
    cudaGetSymbolAddress((void**)&pheads, g_heads);
    cudaGetSymbolAddress((void**)&pao,    g_ao);

    cudaFuncSetAttribute(gemm_qkv, cudaFuncAttributeMaxDynamicSharedMemorySize, G_SMEM);
    cudaFuncSetAttribute(gemm_out, cudaFuncAttributeMaxDynamicSharedMemorySize, G_SMEM);
    cudaFuncSetAttribute(attn_mma, cudaFuncAttributeMaxDynamicSharedMemorySize, AT_SMEM);

    // 1) all weight transposes
    dim3 wgrid(32, 32, 4), wblk(32, 8);
    conv_wt4<<<wgrid, wblk>>>(Wq, Wk, Wv, Wo, pwt);

    // 2) all activation conversions
    dim3 cgrid(MM, 3);
    conv_act3<<<cgrid, 256>>>(query, key, value, pacts);

    // 3) fused QKV projection GEMM
    QkvArgs qa;
    qa.A = pacts; qa.W = pwt; qa.outH = pheads;
    qa.bias[0] = bq; qa.bias[1] = bk; qa.bias[2] = bv;
    dim3 ggrid(AD / 128, MM / 128, 3);   // (8, 64, 3)
    gemm_qkv<<<ggrid, 256, G_SMEM>>>(qa);

    // 4) attention
    dim3 agrid(LL / 64, NH, BB);         // (32, 16, 4)
    attn_mma<<<agrid, 128, AT_SMEM>>>(pheads,
                                      pheads + (size_t)MM * AD,
                                      pheads + 2 * (size_t)MM * AD,
                                      pao);

    // 5) output projection
    dim3 ogrid(AD / 128, MM / 128);      // (8, 64)
    gemm_out<<<ogrid, 256, G_SMEM>>>(pao, pwt + 3 * (size_t)AD * AD, bo, out);
}

// round 16
// speedup vs baseline: 1.0175x; 1.0175x over previous
#include <cuda_runtime.h>
#include <cuda_fp16.h>
#include <cstdint>

// Problem constants
#define BB   4
#define LL   2048
#define AD   1024
#define NH   16
#define HD   64
#define MM   (BB*LL)   // 8192

// ---------------------------------------------------------------------------
// Scratch (device globals)
// ---------------------------------------------------------------------------
__device__ __half g_acts [3 * MM * AD];    // fp16 activations q|k|v
__device__ __half g_wt   [4 * AD * AD];    // weights^T fp16 (q,k,v,o)
__device__ __half g_heads[3 * MM * AD];    // head planes Q(prescaled)|K|V
__device__ __half g_ao   [MM * AD];        // attention output fp16 [M,1024]

// ---------------------------------------------------------------------------
// Helpers (plain sm_103-legal: cp.async, ldmatrix, mma.sync)
// ---------------------------------------------------------------------------
__device__ __forceinline__ uint32_t smem_u32(const void* p) {
    uint32_t a;
    asm("{ .reg .u64 t; cvta.to.shared.u64 t, %1; cvt.u32.u64 %0, t; }" : "=r"(a) : "l"(p));
    return a;
}
#define CP_COMMIT()  asm volatile("cp.async.commit_group;" ::: "memory")
#define CP_WAIT(n)   asm volatile("cp.async.wait_group %0;" :: "n"(n) : "memory")

__device__ __forceinline__ uint32_t pack_h2(__half a, __half b) {
    return (uint32_t)__half_as_ushort(a) | ((uint32_t)__half_as_ushort(b) << 16);
}
__device__ __forceinline__ uint32_t h2_u(__half2 v) { return *reinterpret_cast<uint32_t*>(&v); }
__device__ __forceinline__ __half2  u_h2(uint32_t v) { return *reinterpret_cast<__half2*>(&v); }

__device__ __forceinline__ void ldm_x4(uint32_t& r0, uint32_t& r1, uint32_t& r2, uint32_t& r3,
                                       uint32_t addr) {
    asm volatile("ldmatrix.sync.aligned.m8n8.x4.shared.b16 {%0,%1,%2,%3}, [%4];"
                 : "=r"(r0), "=r"(r1), "=r"(r2), "=r"(r3) : "r"(addr));
}
__device__ __forceinline__ void ldm_x4_t(uint32_t& r0, uint32_t& r1, uint32_t& r2, uint32_t& r3,
                                         uint32_t addr) {
    asm volatile("ldmatrix.sync.aligned.m8n8.x4.trans.shared.b16 {%0,%1,%2,%3}, [%4];"
                 : "=r"(r0), "=r"(r1), "=r"(r2), "=r"(r3) : "r"(addr));
}
// fp32-accumulator mma
__device__ __forceinline__ void mma16816(float* d, const uint32_t* a, uint32_t b0, uint32_t b1) {
    asm volatile(
        "mma.sync.aligned.m16n8k16.row.col.f32.f16.f16.f32 "
        "{%0,%1,%2,%3}, {%4,%5,%6,%7}, {%8,%9}, {%0,%1,%2,%3};"
        : "+f"(d[0]), "+f"(d[1]), "+f"(d[2]), "+f"(d[3])
        : "r"(a[0]), "r"(a[1]), "r"(a[2]), "r"(a[3]), "r"(b0), "r"(b1));
}
// fp16-accumulator mma (d packed half2 x2; layout == A-fragment layout)
__device__ __forceinline__ void mma16816h(uint32_t* d, const uint32_t* a, uint32_t b0, uint32_t b1) {
    asm volatile(
        "mma.sync.aligned.m16n8k16.row.col.f16.f16.f16.f16 "
        "{%0,%1}, {%2,%3,%4,%5}, {%6,%7}, {%0,%1};"
        : "+r"(d[0]), "+r"(d[1])
        : "r"(a[0]), "r"(a[1]), "r"(a[2]), "r"(a[3]), "r"(b0), "r"(b1));
}

// ---------------------------------------------------------------------------
// conv_act fused: 3 inputs fp32 [M,1024] -> fp16, selected by blockIdx.y
// ---------------------------------------------------------------------------
__global__ void conv_act3(const float* __restrict__ X0, const float* __restrict__ X1,
                          const float* __restrict__ X2, __half* __restrict__ Y)
{
    const int z = blockIdx.y;
    const float* X = (z == 0) ? X0 : (z == 1) ? X1 : X2;
    int m = blockIdx.x;
    int c = threadIdx.x * 4;
    float4 v = *reinterpret_cast<const float4*>(X + (size_t)m * AD + c);
    uint2 o;
    o.x = pack_h2(__float2half_rn(v.x), __float2half_rn(v.y));
    o.y = pack_h2(__float2half_rn(v.z), __float2half_rn(v.w));
    *reinterpret_cast<uint2*>(Y + (size_t)z * MM * AD + (size_t)m * AD + c) = o;
}

// ---------------------------------------------------------------------------
// conv_wt fused: 4 weights W[K][N] fp32 -> Wt[N][K] fp16, selected by blockIdx.z
// ---------------------------------------------------------------------------
__global__ void conv_wt4(const float* __restrict__ W0, const float* __restrict__ W1,
                         const float* __restrict__ W2, const float* __restrict__ W3,
                         __half* __restrict__ WtBase)
{
    __shared__ float s[32][33];
    const int z = blockIdx.z;
    const float* W = (z == 0) ? W0 : (z == 1) ? W1 : (z == 2) ? W2 : W3;
    __half* Wt = WtBase + (size_t)z * AD * AD;
    int n0 = blockIdx.x * 32;
    int k0 = blockIdx.y * 32;
    int tx = threadIdx.x, ty = threadIdx.y;   // (32, 8)
#pragma unroll
    for (int i = 0; i < 4; ++i)
        s[ty + 8 * i][tx] = W[(size_t)(k0 + ty + 8 * i) * AD + n0 + tx];
    __syncthreads();
#pragma unroll
    for (int i = 0; i < 4; ++i) {
        int n = n0 + ty + 8 * i;
        int k = k0 + tx;
        Wt[(size_t)n * AD + k] = __float2half_rn(s[tx][ty + 8 * i]);
    }
}

// ---------------------------------------------------------------------------
// fp16 mma GEMM core — R12 2-stage double buffer (proven fastest).
// ---------------------------------------------------------------------------
#define GK_NC 16
#define SA0   0
#define SA1   16384
#define SB0   32768
#define SB1   49152
#define G_SMEM 65536

__device__ __forceinline__ void load_tile_cp(uint32_t sbase, uint32_t soff,
                                             const __half* __restrict__ g,
                                             int row0, int kc, int tid)
{
#pragma unroll
    for (int i = 0; i < 4; ++i) {
        int idx = i * 256 + tid;
        int r = idx >> 3, seg = idx & 7;
        const char* src = (const char*)g + ((size_t)(row0 + r) * AD + kc) * 2 + seg * 16;
        uint32_t dst = sbase + soff + r * 128 + ((seg * 16) ^ ((r & 7) * 16));
        asm volatile("cp.async.cg.shared.global [%0], [%1], 16;" :: "r"(dst), "l"(src));
    }
}

__device__ __forceinline__ void gemm_body(const __half* __restrict__ A,
                                          const __half* __restrict__ Bt,
                                          const float* __restrict__ bias,
                                          float* __restrict__ C,
                                          __half* __restrict__ outH,
                                          float oscale,
                                          char* smem)
{
    const uint32_t sbase = smem_u32(smem);
    const int tid  = threadIdx.x;
    const int warp = tid >> 5;
    const int lane = tid & 31;
    const int bn = blockIdx.x * 128;
    const int bm = blockIdx.y * 128;

    const int wm0 = (warp >> 2) * 64;
    const int wn0 = (warp & 3) * 32;

    float d[4][4][4];
#pragma unroll
    for (int im = 0; im < 4; ++im)
#pragma unroll
        for (int jt = 0; jt < 4; ++jt)
#pragma unroll
            for (int q = 0; q < 4; ++q) d[im][jt][q] = 0.f;

    uint32_t a_rb[4], a_sw[4];
#pragma unroll
    for (int im = 0; im < 4; ++im) {
        int row = wm0 + im * 16 + (lane & 15);
        a_rb[im] = row * 128;
        a_sw[im] = (row & 7) * 16;
    }
    const uint32_t a_kb = (lane >> 4) * 16;
    uint32_t b_rb[2], b_sw[2];
#pragma unroll
    for (int jn = 0; jn < 2; ++jn) {
        int row = wn0 + jn * 16 + (lane & 7) + ((lane >> 4) << 3);
        b_rb[jn] = row * 128;
        b_sw[jn] = (row & 7) * 16;
    }
    const uint32_t b_kb = ((lane >> 3) & 1) * 16;

    load_tile_cp(sbase, SA0, A,  bm, 0, tid);
    load_tile_cp(sbase, SB0, Bt, bn, 0, tid);
    CP_COMMIT();

    for (int i = 0; i < GK_NC; ++i) {
        const uint32_t aoff = (i & 1) ? SA1 : SA0;
        const uint32_t boff = (i & 1) ? SB1 : SB0;
        if (i + 1 < GK_NC) {
            load_tile_cp(sbase, (i & 1) ? SA0 : SA1, A,  bm, (i + 1) * 64, tid);
            load_tile_cp(sbase, (i & 1) ? SB0 : SB1, Bt, bn, (i + 1) * 64, tid);
            CP_COMMIT();
            CP_WAIT(1);
        } else {
            CP_WAIT(0);
        }
        __syncthreads();

#pragma unroll
        for (int ks = 0; ks < 4; ++ks) {
            const uint32_t kb = ks * 32;
            uint32_t af[4][4];
#pragma unroll
            for (int im = 0; im < 4; ++im)
                ldm_x4(af[im][0], af[im][1], af[im][2], af[im][3],
                       sbase + aoff + a_rb[im] + ((kb + a_kb) ^ a_sw[im]));
            uint32_t bf[4][2];
#pragma unroll
            for (int jn = 0; jn < 2; ++jn) {
                uint32_t r0, r1, r2, r3;
                ldm_x4(r0, r1, r2, r3,
                       sbase + boff + b_rb[jn] + ((kb + b_kb) ^ b_sw[jn]));
                bf[jn * 2][0] = r0; bf[jn * 2][1] = r1;
                bf[jn * 2 + 1][0] = r2; bf[jn * 2 + 1][1] = r3;
            }
#pragma unroll
            for (int im = 0; im < 4; ++im)
#pragma unroll
                for (int jt = 0; jt < 4; ++jt)
                    mma16816(d[im][jt], af[im], bf[jt][0], bf[jt][1]);
        }
        __syncthreads();
    }

    if (outH == nullptr) {
#pragma unroll
        for (int jt = 0; jt < 4; ++jt) {
            const int c0 = bn + wn0 + jt * 8 + 2 * (lane & 3);
            float2 bb = *reinterpret_cast<const float2*>(bias + c0);
#pragma unroll
            for (int im = 0; im < 4; ++im) {
                const int r0 = bm + wm0 + im * 16 + (lane >> 2);
                float2 o0 = make_float2(d[im][jt][0] + bb.x, d[im][jt][1] + bb.y);
                float2 o1 = make_float2(d[im][jt][2] + bb.x, d[im][jt][3] + bb.y);
                *reinterpret_cast<float2*>(C + (size_t)r0 * AD + c0)       = o0;
                *reinterpret_cast<float2*>(C + (size_t)(r0 + 8) * AD + c0) = o1;
            }
        }
    } else {
        // fp16 head-plane epilogue: [(b*NH+h)][L][64]
#pragma unroll
        for (int jt = 0; jt < 4; ++jt) {
            const int c0 = bn + wn0 + jt * 8 + 2 * (lane & 3);
            float2 bb = *reinterpret_cast<const float2*>(bias + c0);
            const int hh = c0 >> 6, dd = c0 & 63;
#pragma unroll
            for (int im = 0; im < 4; ++im) {
                const int r0 = bm + wm0 + im * 16 + (lane >> 2);
#pragma unroll
                for (int half = 0; half < 2; ++half) {
                    const int r = r0 + half * 8;
                    float v0 = (d[im][jt][half * 2 + 0] + bb.x) * oscale;
                    float v1 = (d[im][jt][half * 2 + 1] + bb.y) * oscale;
                    size_t addr = ((size_t)((r >> 11) * NH + hh) * LL + (r & 2047)) * HD + dd;
                    *reinterpret_cast<uint32_t*>(outH + addr) =
                        pack_h2(__float2half_rn(v0), __float2half_rn(v1));
                }
            }
        }
    }
}

// Fused QKV wrapper: blockIdx.z in {0,1,2} selects the projection.
struct QkvArgs {
    const __half* A;
    const __half* W;
    const float*  bias[3];
    __half*       outH;
};

// Q prescale folds softmax scale AND log2(e) so attention works in base-2.
#define Q_PRESCALE (0.125f * 1.4426950408889634f)

__global__ __launch_bounds__(256, 2)
void gemm_qkv(QkvArgs a)
{
    extern __shared__ char smem[];
    const int z = blockIdx.z;
    const float oscale = (z == 0) ? Q_PRESCALE : 1.0f;
    gemm_body(a.A + (size_t)z * MM * AD,
              a.W + (size_t)z * AD * AD,
              a.bias[z],
              nullptr,
              a.outH + (size_t)z * MM * AD,
              oscale, smem);
}

__global__ __launch_bounds__(256, 2)
void gemm_out(const __half* __restrict__ A, const __half* __restrict__ Bt,
              const float* __restrict__ bias, float* __restrict__ C)
{
    extern __shared__ char smem[];
    gemm_body(A, Bt, bias, C, nullptr, 1.0f, smem);
}

// ---------------------------------------------------------------------------
// fp16 mma flash attention — R14 split-KV + warp-uniform rescale skip.
// When every lane's corr == 1.0 (max unchanged, the common case after a few
// chunks), the entire O/Ol rescale block is skipped; otherwise all lanes
// rescale (x *= 1.0f is bit-identical) -> results identical to R14.
// ---------------------------------------------------------------------------
#define AT_Q   0
#define AT_BUF 8192
#define AT_SMEM (8192 + 2*32768)        // 73728 ; x3 CTAs = 216KB <= 228KB

__device__ __forceinline__ void at_load_plane(uint32_t sb, uint32_t soff,
                                              const __half* __restrict__ g,
                                              size_t pbase, int row0, int nrows, int tid)
{
    const int iters = nrows / 16;
#pragma unroll
    for (int i = 0; i < 8; ++i) {
        if (i >= iters) break;
        int idx = i * 128 + tid;
        int r = idx >> 3, seg = idx & 7;
        const char* src = (const char*)(g + pbase + (size_t)(row0 + r) * HD) + seg * 16;
        uint32_t dst = sb + soff + r * 128 + ((seg * 16) ^ ((r & 7) * 16));
        asm volatile("cp.async.cg.shared.global [%0], [%1], 16;" :: "r"(dst), "l"(src));
    }
}

__global__ __launch_bounds__(128, 3)
void attn_mma(const __half* __restrict__ Qh,
              const __half* __restrict__ Kh,
              const __half* __restrict__ Vh,
              __half* __restrict__ Oatt)
{
    extern __shared__ char smem[];
    const uint32_t sb = smem_u32(smem);
    const int tid  = threadIdx.x;
    const int warp = tid >> 5;
    const int lane = tid & 31;
    const int gidr = lane >> 2;
    const int tg   = lane & 3;
    const int qh   = warp & 1;
    const int kvh  = warp >> 1;

    const int qt = blockIdx.x, h = blockIdx.y, b = blockIdx.z;
    const size_t pbase = (size_t)(b * NH + h) * LL * HD;
    const int q0 = qt * 64;

    at_load_plane(sb, AT_Q, Qh, pbase, q0, 64, tid);
    CP_COMMIT();
    at_load_plane(sb, AT_BUF,         Kh, pbase, 0, 128, tid);
    at_load_plane(sb, AT_BUF + 16384, Vh, pbase, 0, 128, tid);
    CP_COMMIT();
    at_load_plane(sb, AT_BUF + 32768, Kh, pbase, 128, 128, tid);
    at_load_plane(sb, AT_BUF + 49152, Vh, pbase, 128, 128, tid);
    CP_COMMIT();

    const uint32_t a_kb = (lane >> 4) * 16;
    uint32_t q_off[2], q_sw[2];
#pragma unroll
    for (int im = 0; im < 2; ++im) {
        const uint32_t row = 32 * qh + 16 * im + (lane & 15);
        q_off[im] = row * 128;
        q_sw[im]  = (row & 7) * 16;
    }

    const uint32_t b_rowb = (lane & 7) + ((lane >> 4) << 3);
    const uint32_t b_kb   = ((lane >> 3) & 1) * 16;
    const uint32_t v_rowb = (lane & 15);
    const uint32_t v_cb   = (lane >> 4) * 16;

    const uint32_t ones = ((lane >> 2) == 0) ? 0x3C003C00u : 0u;

    float m[2][2];
    m[0][0] = m[0][1] = m[1][0] = m[1][1] = -1e30f;
    float O[2][8][4];
    float Ol[2][4];
#pragma unroll
    for (int im = 0; im < 2; ++im) {
#pragma unroll
        for (int jn = 0; jn < 8; ++jn)
#pragma unroll
            for (int q = 0; q < 4; ++q) O[im][jn][q] = 0.f;
#pragma unroll
        for (int q = 0; q < 4; ++q) Ol[im][q] = 0.f;
    }

    for (int ci = 0; ci < 16; ++ci) {
        if (ci < 15) { CP_WAIT(1); } else { CP_WAIT(0); }
        __syncthreads();

        const uint32_t kh_ = sb + AT_BUF + (ci & 1) * 32768;
        const uint32_t vh_ = kh_ + 16384;

        uint32_t sh[2][8][2];
#pragma unroll
        for (int im = 0; im < 2; ++im)
#pragma unroll
            for (int jn = 0; jn < 8; ++jn) { sh[im][jn][0] = 0u; sh[im][jn][1] = 0u; }

#pragma unroll
        for (int ks = 0; ks < 4; ++ks) {
            const uint32_t kb = ks * 32;
            uint32_t qf0[4], qf1[4];
            ldm_x4(qf0[0], qf0[1], qf0[2], qf0[3],
                   sb + AT_Q + q_off[0] + ((kb + a_kb) ^ q_sw[0]));
            ldm_x4(qf1[0], qf1[1], qf1[2], qf1[3],
                   sb + AT_Q + q_off[1] + ((kb + a_kb) ^ q_sw[1]));
#pragma unroll
            for (int jt = 0; jt < 4; ++jt) {
                const uint32_t row = 64 * kvh + 16 * jt + b_rowb;
                uint32_t r0, r1, r2, r3;
                ldm_x4(r0, r1, r2, r3, kh_ + row * 128 + ((kb + b_kb) ^ ((row & 7) * 16)));
                mma16816h(sh[0][2 * jt],     qf0, r0, r1);
                mma16816h(sh[0][2 * jt + 1], qf0, r2, r3);
                mma16816h(sh[1][2 * jt],     qf1, r0, r1);
                mma16816h(sh[1][2 * jt + 1], qf1, r2, r3);
            }
        }

#pragma unroll
        for (int im = 0; im < 2; ++im) {
            __half2 cx0 = u_h2(sh[im][0][0]), cx1 = u_h2(sh[im][0][1]);
#pragma unroll
            for (int jn = 1; jn < 8; ++jn) {
                cx0 = __hmax2(cx0, u_h2(sh[im][jn][0]));
                cx1 = __hmax2(cx1, u_h2(sh[im][jn][1]));
            }
            float cm0 = fmaxf(__low2float(cx0), __high2float(cx0));
            float cm1 = fmaxf(__low2float(cx1), __high2float(cx1));
            cm0 = fmaxf(cm0, __shfl_xor_sync(0xffffffffu, cm0, 1));
            cm0 = fmaxf(cm0, __shfl_xor_sync(0xffffffffu, cm0, 2));
            cm1 = fmaxf(cm1, __shfl_xor_sync(0xffffffffu, cm1, 1));
            cm1 = fmaxf(cm1, __shfl_xor_sync(0xffffffffu, cm1, 2));
            const float mn0 = fmaxf(m[im][0], cm0);
            const float mn1 = fmaxf(m[im][1], cm1);
            const float corr0 = exp2f(m[im][0] - mn0);
            const float corr1 = exp2f(m[im][1] - mn1);
            m[im][0] = mn0; m[im][1] = mn1;

            // warp-uniform rescale skip: bit-identical (x *= 1.0f is identity)
            const bool need = !__all_sync(0xffffffffu,
                                          (corr0 == 1.0f) && (corr1 == 1.0f));
            if (need) {
#pragma unroll
                for (int jn = 0; jn < 8; ++jn) {
                    O[im][jn][0] *= corr0; O[im][jn][1] *= corr0;
                    O[im][jn][2] *= corr1; O[im][jn][3] *= corr1;
                }
                Ol[im][0] *= corr0; Ol[im][1] *= corr0;
                Ol[im][2] *= corr1; Ol[im][3] *= corr1;
            }

            const __half2 mh0 = __floats2half2_rn(mn0, mn0);
            const __half2 mh1 = __floats2half2_rn(mn1, mn1);
#pragma unroll
            for (int jn = 0; jn < 8; ++jn) {
                sh[im][jn][0] = h2_u(h2exp2(__hsub2(u_h2(sh[im][jn][0]), mh0)));
                sh[im][jn][1] = h2_u(h2exp2(__hsub2(u_h2(sh[im][jn][1]), mh1)));
            }
        }

#pragma unroll
        for (int kk = 0; kk < 4; ++kk) {
            uint32_t ah0[4] = { sh[0][2*kk][0], sh[0][2*kk][1], sh[0][2*kk+1][0], sh[0][2*kk+1][1] };
            uint32_t ah1[4] = { sh[1][2*kk][0], sh[1][2*kk][1], sh[1][2*kk+1][0], sh[1][2*kk+1][1] };

            mma16816(Ol[0], ah0, ones, ones);
            mma16816(Ol[1], ah1, ones, ones);

            const uint32_t vrow = 64 * kvh + 16 * kk + v_rowb;
            const uint32_t vsw  = (vrow & 7) * 16;
            const uint32_t vaddr = vh_ + vrow * 128;
#pragma unroll
            for (int nb = 0; nb < 4; ++nb) {
                uint32_t r0, r1, r2, r3;
                ldm_x4_t(r0, r1, r2, r3, vaddr + (((uint32_t)(nb * 32) + v_cb) ^ vsw));
                mma16816(O[0][2 * nb],     ah0, r0, r1);
                mma16816(O[0][2 * nb + 1], ah0, r2, r3);
                mma16816(O[1][2 * nb],     ah1, r0, r1);
                mma16816(O[1][2 * nb + 1], ah1, r2, r3);
            }
        }

        __syncthreads();
        if (ci + 2 < 16) {
            uint32_t bb = AT_BUF + (ci & 1) * 32768;
            int row0 = (ci + 2) * 128;
            at_load_plane(sb, bb,         Kh, pbase, row0, 128, tid);
            at_load_plane(sb, bb + 16384, Vh, pbase, row0, 128, tid);
            CP_COMMIT();
        }
    }

    float lw[2][2];
#pragma unroll
    for (int im = 0; im < 2; ++im) {
        lw[im][0] = __shfl_sync(0xffffffffu, Ol[im][0], lane & 28);
        lw[im][1] = __shfl_sync(0xffffffffu, Ol[im][2], lane & 28);
    }

    if (kvh == 1) {
        float* dst = reinterpret_cast<float*>(smem + AT_BUF + qh * 9216) + lane * 72;
#pragma unroll
        for (int im = 0; im < 2; ++im)
#pragma unroll
            for (int jn = 0; jn < 8; ++jn)
#pragma unroll
                for (int q = 0; q < 4; ++q)
                    dst[im * 32 + jn * 4 + q] = O[im][jn][q];
        dst[64] = m[0][0]; dst[65] = m[0][1]; dst[66] = m[1][0]; dst[67] = m[1][1];
        dst[68] = lw[0][0]; dst[69] = lw[0][1]; dst[70] = lw[1][0]; dst[71] = lw[1][1];
    }
    __syncthreads();
    if (kvh == 0) {
        const float* src = reinterpret_cast<const float*>(smem + AT_BUF + qh * 9216) + lane * 72;
        const int colb = h * HD + 2 * tg;
#pragma unroll
        for (int im = 0; im < 2; ++im) {
#pragma unroll
            for (int half = 0; half < 2; ++half) {
                const float mA = m[im][half];
                const float mB = src[64 + im * 2 + half];
                const float ms = fmaxf(mA, mB);
                const float cA = exp2f(mA - ms);
                const float cB = exp2f(mB - ms);
                const float linv = 1.f / (lw[im][half] * cA + src[68 + im * 2 + half] * cB);
                const int r = q0 + 32 * qh + 16 * im + gidr + 8 * half;
                const int qb = half * 2;
#pragma unroll
                for (int jn = 0; jn < 8; ++jn) {
                    float v0 = (O[im][jn][qb]     * cA + src[im * 32 + jn * 4 + qb]     * cB) * linv;
                    float v1 = (O[im][jn][qb + 1] * cA + src[im * 32 + jn * 4 + qb + 1] * cB) * linv;
                    size_t addr = (size_t)(b * LL + r) * AD + colb + 8 * jn;
                    *reinterpret_cast<uint32_t*>(Oatt + addr) =
                        pack_h2(__float2half_rn(v0), __float2half_rn(v1));
                }
            }
        }
    }
}

// ---------------------------------------------------------------------------
// Launch: 5 kernels total
// ---------------------------------------------------------------------------
extern "C" void kernel_launch(void* const* d_in, const int* in_sizes, int n_in,
                              void* d_out, int out_size)
{
    const float* query = (const float*)d_in[0];
    const float* key   = (const float*)d_in[1];
    const float* value = (const float*)d_in[2];
    const float* Wq = (const float*)d_in[3];
    const float* bq = (const float*)d_in[4];
    const float* Wk = (const float*)d_in[5];
    const float* bk = (const float*)d_in[6];
    const float* Wv = (const float*)d_in[7];
    const float* bv = (const float*)d_in[8];
    const float* Wo = (const float*)d_in[9];
    const float* bo = (const float*)d_in[10];
    float* out = (float*)d_out;

    __half *pacts, *pwt, *pheads, *pao;
    cudaGetSymbolAddress((void**)&pacts,  g_acts);
    cudaGetSymbolAddress((void**)&pwt,    g_wt);
    cudaGetSymbolAddress((void**)&pheads, g_heads);
    cudaGetSymbolAddress((void**)&pao,    g_ao);

    cudaFuncSetAttribute(gemm_qkv, cudaFuncAttributeMaxDynamicSharedMemorySize, G_SMEM);
    cudaFuncSetAttribute(gemm_out, cudaFuncAttributeMaxDynamicSharedMemorySize, G_SMEM);
    cudaFuncSetAttribute(attn_mma, cudaFuncAttributeMaxDynamicSharedMemorySize, AT_SMEM);

    // 1) all weight transposes
    dim3 wgrid(32, 32, 4), wblk(32, 8);
    conv_wt4<<<wgrid, wblk>>>(Wq, Wk, Wv, Wo, pwt);

    // 2) all activation conversions
    dim3 cgrid(MM, 3);
    conv_act3<<<cgrid, 256>>>(query, key, value, pacts);

    // 3) fused QKV projection GEMM
    QkvArgs qa;
    qa.A = pacts; qa.W = pwt; qa.outH = pheads;
    qa.bias[0] = bq; qa.bias[1] = bk; qa.bias[2] = bv;
    dim3 ggrid(AD / 128, MM / 128, 3);   // (8, 64, 3)
    gemm_qkv<<<ggrid, 256, G_SMEM>>>(qa);

    // 4) attention
    dim3 agrid(LL / 64, NH, BB);         // (32, 16, 4)
    attn_mma<<<agrid, 128, AT_SMEM>>>(pheads,
                                      pheads + (size_t)MM * AD,
                                      pheads + 2 * (size_t)MM * AD,
                                      pao);

    // 5) output projection
    dim3 ogrid(AD / 128, MM / 128);      // (8, 64)
    gemm_out<<<ogrid, 256, G_SMEM>>>(pao, pwt + 3 * (size_t)AD * AD, bo, out);
}